// round 1
// baseline (speedup 1.0000x reference)
#include <cuda_runtime.h>
#include <math.h>

// Problem constants
#define B_    4
#define C_    64
#define H_    128
#define W_    128
#define HW_   (H_*W_)
#define OFFC_ 32
#define K2_   9
#define OCOFF 27   // 3*K*K offset-conv output channels

// ---------------- scratch (device globals: no allocation allowed) ----------------
// Per (b,k,y,x): bilinear corner linear indices (clamped, within one HxW plane)
// and weights premultiplied by validity and mask.
__device__ int4   g_idx[B_ * K2_ * HW_];
__device__ float4 g_wts[B_ * K2_ * HW_];
// weight transposed to [k][c][o]
__device__ float  g_wt[K2_ * C_ * C_];

// ---------------- Stage 0: transpose weight [o][c][k] -> [k][c][o] ----------------
__global__ void transpose_w_kernel(const float* __restrict__ w) {
    int i = blockIdx.x * 256 + threadIdx.x;       // over 64*64*9 = 36864
    if (i < C_ * C_ * K2_) {
        int o = i / (C_ * K2_);
        int r = i % (C_ * K2_);
        int c = r / K2_;
        int k = r % K2_;
        g_wt[(k * C_ + c) * C_ + o] = w[i];
    }
}

// ---------------- Stage 1: offset conv + bilinear descriptor precompute ----------------
// grid: B_*H_ blocks, 128 threads (one per output x). Each thread computes the
// 27 offset-conv outputs for its pixel, then derives 9 sampling descriptors.
__global__ __launch_bounds__(128) void offset_kernel(
    const float* __restrict__ offset_feat,   // [B,32,H,W]
    const float* __restrict__ w_off,         // [27,32,3,3]
    const float* __restrict__ b_off)         // [27]
{
    // smem: w_off transposed to [c*9+tap][28] for float4 broadcast loads
    __shared__ float s_w[OFFC_ * 32 * 9 / 27 * 28];   // placeholder sizing below
    // (actual size: 288 rows * 28 cols)
    __shared__ float s_boff[28];

    const int tid = threadIdx.x;
    const int y   = blockIdx.x & (H_ - 1);
    const int b   = blockIdx.x >> 7;
    const int x   = tid;

    // cooperative load of w_off -> s_w[(c*9+tap)*28 + oc]
    for (int i = tid; i < OCOFF * 288; i += 128) {
        int oc = i / 288;
        int r  = i % 288;             // c*9 + tap
        s_w[r * 28 + oc] = w_off[i];
    }
    if (tid < 28) s_boff[tid] = (tid < OCOFF) ? b_off[tid] : 0.f;
    __syncthreads();

    float acc[28];
#pragma unroll
    for (int j = 0; j < 28; j++) acc[j] = s_boff[j];

    const float* fbase = offset_feat + (size_t)b * OFFC_ * HW_;

#pragma unroll
    for (int ky = 0; ky < 3; ky++) {
        const int iy = y - 1 + ky;
        const bool vy = ((unsigned)iy < (unsigned)H_);
#pragma unroll
        for (int kx = 0; kx < 3; kx++) {
            const int ix = x - 1 + kx;
            const bool v = vy && ((unsigned)ix < (unsigned)W_);
            const int tap = ky * 3 + kx;
            const float* ip = fbase + iy * W_ + ix;
#pragma unroll 4
            for (int c = 0; c < OFFC_; c++) {
                float vv = v ? __ldg(ip + c * HW_) : 0.f;
                const float4* wp = (const float4*)(s_w + (c * 9 + tap) * 28);
#pragma unroll
                for (int j = 0; j < 7; j++) {
                    float4 w4 = wp[j];
                    acc[j * 4 + 0] += vv * w4.x;
                    acc[j * 4 + 1] += vv * w4.y;
                    acc[j * 4 + 2] += vv * w4.z;
                    acc[j * 4 + 3] += vv * w4.w;
                }
            }
        }
    }

    // derive sampling descriptors per tap
#pragma unroll
    for (int k = 0; k < K2_; k++) {
        float dy = acc[2 * k];
        float dx = acc[2 * k + 1];
        float m  = 1.f / (1.f + __expf(-acc[18 + k]));

        float py = (float)(y - 1 + (k / 3)) + dy;
        float px = (float)(x - 1 + (k % 3)) + dx;
        float y0f = floorf(py), x0f = floorf(px);
        float wy1 = py - y0f,   wx1 = px - x0f;
        float wy0 = 1.f - wy1,  wx0 = 1.f - wx1;
        int y0 = (int)y0f, x0 = (int)x0f;
        int y1 = y0 + 1,   x1 = x0 + 1;

        bool vy0 = ((unsigned)y0 < (unsigned)H_);
        bool vy1 = ((unsigned)y1 < (unsigned)H_);
        bool vx0 = ((unsigned)x0 < (unsigned)W_);
        bool vx1 = ((unsigned)x1 < (unsigned)W_);

        float w00 = wy0 * wx0 * m * (float)(vy0 && vx0);
        float w01 = wy0 * wx1 * m * (float)(vy0 && vx1);
        float w10 = wy1 * wx0 * m * (float)(vy1 && vx0);
        float w11 = wy1 * wx1 * m * (float)(vy1 && vx1);

        int y0c = min(max(y0, 0), H_ - 1);
        int y1c = min(max(y1, 0), H_ - 1);
        int x0c = min(max(x0, 0), W_ - 1);
        int x1c = min(max(x1, 0), W_ - 1);

        int base = ((b * K2_ + k) * H_ + y) * W_ + x;
        g_idx[base] = make_int4(y0c * W_ + x0c, y0c * W_ + x1c,
                                y1c * W_ + x0c, y1c * W_ + x1c);
        g_wts[base] = make_float4(w00, w01, w10, w11);
    }
}

// ---------------- Stage 2: fused sampling + GEMM ----------------
// block = one (b,y) output row (128 px). Per tap k:
//   fill smem S_k[64c x 128p] via bilinear gather, load W_k[64c x 64o],
//   accumulate 64x128 register-tiled GEMM (4o x 8p per thread).
__global__ __launch_bounds__(256, 3) void deform_kernel(
    const float* __restrict__ x,     // [B,64,H,W]
    const float* __restrict__ bias,  // [64]
    float* __restrict__ out)         // [B,64,H,W]
{
    __shared__ float sW[C_ * C_];        // [c][o]   16 KB
    __shared__ float sS[C_ * W_];        // [c][p]   32 KB

    const int tid = threadIdx.x;
    const int y   = blockIdx.x & (H_ - 1);
    const int b   = blockIdx.x >> 7;

    // fill-phase mapping: warp fw, lane fl -> fixed pixel fp, channel range fc0
    const int fw  = tid >> 5;
    const int fl  = tid & 31;
    const int fp  = (fw & 3) * 32 + fl;      // 0..127
    const int fc0 = (fw >> 2) * 32;          // 0 or 32

    // gemm-phase mapping
    const int tx = tid & 15;                 // pixel group
    const int ty = tid >> 4;                 // o group
    const int p0 = tx * 8;
    const int o0 = ty * 4;

    float acc[4][8];
#pragma unroll
    for (int i = 0; i < 4; i++)
#pragma unroll
        for (int j = 0; j < 8; j++) acc[i][j] = 0.f;

    const float* xb = x + (size_t)b * C_ * HW_;

#pragma unroll 1
    for (int k = 0; k < K2_; k++) {
        // load W_k [c][o] coalesced from pre-transposed g_wt
        const float* wk = g_wt + k * C_ * C_;
#pragma unroll
        for (int i = 0; i < 16; i++)
            sW[tid + i * 256] = wk[tid + i * 256];

        // bilinear fill of S_k
        const int ib = ((b * K2_ + k) * H_ + y) * W_ + fp;
        const float4 wv = g_wts[ib];
        const int4   iv = g_idx[ib];
#pragma unroll 4
        for (int c = 0; c < 32; c++) {
            const float* cp = xb + (fc0 + c) * HW_;
            float v = wv.x * __ldg(cp + iv.x)
                    + wv.y * __ldg(cp + iv.y)
                    + wv.z * __ldg(cp + iv.z)
                    + wv.w * __ldg(cp + iv.w);
            sS[(fc0 + c) * W_ + fp] = v;
        }
        __syncthreads();

        // GEMM: acc[4][8] += W_k[c][o0..o0+3] * S_k[c][p0..p0+7]
#pragma unroll 8
        for (int c = 0; c < C_; c++) {
            float4 w4 = *(const float4*)&sW[c * C_ + o0];
            float4 s0 = *(const float4*)&sS[c * W_ + p0];
            float4 s1 = *(const float4*)&sS[c * W_ + p0 + 4];
            acc[0][0] += w4.x * s0.x; acc[0][1] += w4.x * s0.y;
            acc[0][2] += w4.x * s0.z; acc[0][3] += w4.x * s0.w;
            acc[0][4] += w4.x * s1.x; acc[0][5] += w4.x * s1.y;
            acc[0][6] += w4.x * s1.z; acc[0][7] += w4.x * s1.w;
            acc[1][0] += w4.y * s0.x; acc[1][1] += w4.y * s0.y;
            acc[1][2] += w4.y * s0.z; acc[1][3] += w4.y * s0.w;
            acc[1][4] += w4.y * s1.x; acc[1][5] += w4.y * s1.y;
            acc[1][6] += w4.y * s1.z; acc[1][7] += w4.y * s1.w;
            acc[2][0] += w4.z * s0.x; acc[2][1] += w4.z * s0.y;
            acc[2][2] += w4.z * s0.z; acc[2][3] += w4.z * s0.w;
            acc[2][4] += w4.z * s1.x; acc[2][5] += w4.z * s1.y;
            acc[2][6] += w4.z * s1.z; acc[2][7] += w4.z * s1.w;
            acc[3][0] += w4.w * s0.x; acc[3][1] += w4.w * s0.y;
            acc[3][2] += w4.w * s0.z; acc[3][3] += w4.w * s0.w;
            acc[3][4] += w4.w * s1.x; acc[3][5] += w4.w * s1.y;
            acc[3][6] += w4.w * s1.z; acc[3][7] += w4.w * s1.w;
        }
        __syncthreads();
    }

    // epilogue
#pragma unroll
    for (int i = 0; i < 4; i++) {
        float bv = __ldg(&bias[o0 + i]);
        float* op = out + (((size_t)b * C_ + (o0 + i)) * H_ + y) * W_ + p0;
        float4 r0 = make_float4(acc[i][0] + bv, acc[i][1] + bv,
                                acc[i][2] + bv, acc[i][3] + bv);
        float4 r1 = make_float4(acc[i][4] + bv, acc[i][5] + bv,
                                acc[i][6] + bv, acc[i][7] + bv);
        *(float4*)op       = r0;
        *(float4*)(op + 4) = r1;
    }
}

// ---------------- launch ----------------
extern "C" void kernel_launch(void* const* d_in, const int* in_sizes, int n_in,
                              void* d_out, int out_size) {
    const float* x           = (const float*)d_in[0];
    const float* offset_feat = (const float*)d_in[1];
    const float* w_off       = (const float*)d_in[2];
    const float* b_off       = (const float*)d_in[3];
    const float* weight      = (const float*)d_in[4];
    const float* bias        = (const float*)d_in[5];
    float* out = (float*)d_out;

    transpose_w_kernel<<<(C_ * C_ * K2_ + 255) / 256, 256>>>(weight);
    offset_kernel<<<B_ * H_, 128>>>(offset_feat, w_off, b_off);
    deform_kernel<<<B_ * H_, 256>>>(x, bias, out);
}